// round 15
// baseline (speedup 1.0000x reference)
#include <cuda_runtime.h>
#include <cuda_bf16.h>
#include <cstdint>
#include <math.h>

#define BB   2
#define HH   16
#define SSEQ 2048
#define DH   64
#define EMB  1024
#define MTOT (BB * SSEQ)   // 4096
#define WSZ  ((size_t)EMB * EMB)

// ---- scratch (no allocation allowed) ----
__device__ float g_q[(size_t)BB * HH * SSEQ * DH];            // [B,H,S,D] fp32
// pre-split bf16 operands
__device__ __nv_bfloat16 g_xh[(size_t)MTOT * EMB];
__device__ __nv_bfloat16 g_xl[(size_t)MTOT * EMB];
__device__ __nv_bfloat16 g_wh[4 * WSZ];                        // Wq,Wk,Wv,Wo
__device__ __nv_bfloat16 g_wl[4 * WSZ];
__device__ __nv_bfloat16 g_ctx_h[(size_t)MTOT * EMB];          // attn output
__device__ __nv_bfloat16 g_ctx_l[(size_t)MTOT * EMB];
// K' = [K | tanh(K)] bf16 hi/lo split, [bh][s][128]
__device__ __nv_bfloat16 g_kx_h[(size_t)BB * HH * SSEQ * 128];
__device__ __nv_bfloat16 g_kx_l[(size_t)BB * HH * SSEQ * 128];
// V bf16 hi/lo split, [bh][s][64]
__device__ __nv_bfloat16 g_vx_h[(size_t)BB * HH * SSEQ * 64];
__device__ __nv_bfloat16 g_vx_l[(size_t)BB * HH * SSEQ * 64];

// ============================================================================
// helpers
// ============================================================================
__device__ __forceinline__ uint32_t smem_u32(const void* p) {
    uint32_t a;
    asm("{ .reg .u64 t; cvta.to.shared.u64 t, %1; cvt.u32.u64 %0, t; }" : "=r"(a) : "l"(p));
    return a;
}
__device__ __forceinline__ void ldsm4(uint32_t* r, uint32_t addr) {
    asm volatile("ldmatrix.sync.aligned.m8n8.x4.shared.b16 {%0,%1,%2,%3}, [%4];"
        : "=r"(r[0]), "=r"(r[1]), "=r"(r[2]), "=r"(r[3]) : "r"(addr));
}
__device__ __forceinline__ void ldsm4t(uint32_t* r, uint32_t addr) {
    asm volatile("ldmatrix.sync.aligned.m8n8.x4.trans.shared.b16 {%0,%1,%2,%3}, [%4];"
        : "=r"(r[0]), "=r"(r[1]), "=r"(r[2]), "=r"(r[3]) : "r"(addr));
}
// D += A(bf16 m16k16) * B(bf16 k16n8), fp32 accum
__device__ __forceinline__ void mma_bf16(float* d, const uint32_t* a, uint32_t b0, uint32_t b1) {
    asm volatile("mma.sync.aligned.m16n8k16.row.col.f32.bf16.bf16.f32 "
        "{%0,%1,%2,%3}, {%4,%5,%6,%7}, {%8,%9}, {%0,%1,%2,%3};"
        : "+f"(d[0]), "+f"(d[1]), "+f"(d[2]), "+f"(d[3])
        : "r"(a[0]), "r"(a[1]), "r"(a[2]), "r"(a[3]), "r"(b0), "r"(b1));
}
__device__ __forceinline__ uint32_t packbf(float lo, float hi) {
    uint32_t r;
    asm("cvt.rn.bf16x2.f32 %0, %1, %2;" : "=r"(r) : "f"(hi), "f"(lo));
    return r;
}
__device__ __forceinline__ float bflo(uint32_t u) { return __uint_as_float(u << 16); }
__device__ __forceinline__ float bfhi(uint32_t u) { return __uint_as_float(u & 0xffff0000u); }

__device__ __forceinline__ void split4(float4 v, uint32_t& h0, uint32_t& h1,
                                       uint32_t& l0, uint32_t& l1) {
    h0 = packbf(v.x, v.y);
    h1 = packbf(v.z, v.w);
    l0 = packbf(v.x - bflo(h0), v.y - bfhi(h0));
    l1 = packbf(v.z - bflo(h1), v.w - bfhi(h1));
}

__device__ __forceinline__ void cpa16(uint32_t dst, const void* src) {
    asm volatile("cp.async.cg.shared.global [%0], [%1], 16;" :: "r"(dst), "l"(src));
}
#define CP_COMMIT() asm volatile("cp.async.commit_group;" ::: "memory")
#define CP_WAIT1()  asm volatile("cp.async.wait_group 1;" ::: "memory")
#define CP_WAIT0()  asm volatile("cp.async.wait_group 0;" ::: "memory")

// ============================================================================
// pre-pass: fp32 -> bf16 hi/lo residual split (vectorized by float4)
// ============================================================================
__global__ __launch_bounds__(256)
void conv_split(const float* __restrict__ src, __nv_bfloat16* __restrict__ dh,
                __nv_bfloat16* __restrict__ dl, int n4)
{
    int i = blockIdx.x * 256 + threadIdx.x;
    if (i < n4) {
        float4 v = ((const float4*)src)[i];
        uint32_t h0, h1, l0, l1;
        split4(v, h0, h1, l0, l1);
        ((uint2*)dh)[i] = make_uint2(h0, h1);
        ((uint2*)dl)[i] = make_uint2(l0, l1);
    }
}

// ============================================================================
// HMMA GEMM on pre-split bf16 operands: C = A @ W^T + bias.
// Ah/Al [M,1024] bf16 row-major; W selected from g_wh/g_wl (z index).
// CTA tile 128x128, K-chunk 32, 3-stage cp.async pipeline, 8 warps (2Mx4N),
// warp tile 64x32, 3 products per k16: AhBh + AhBl + AlBh.
// smem/stage: Ah,Al,Bh,Bl each 128 rows x 80B stride (64B data + 16B pad,
// conflict-free ldmatrix) = 10240B per tile, 40960B/stage, 3 stages = 120KB.
// OPROJ=0: z = 0(Q fp32 split-head) 1(K -> kx ext + tanh) 2(V -> vx ext)
// OPROJ=1: plain fp32 out (O projection), weights slot 3.
// ============================================================================
template <int OPROJ>
__global__ __launch_bounds__(256, 1)
void gemm_bf16(const __nv_bfloat16* __restrict__ Ah,
               const __nv_bfloat16* __restrict__ Al,
               const float* __restrict__ b0p, const float* __restrict__ b1p,
               const float* __restrict__ b2p, float* __restrict__ Oout)
{
    extern __shared__ __align__(16) char dyn[];
    const int tid = threadIdx.x;
    const int lane = tid & 31;
    const int wid = tid >> 5;
    const int bm = blockIdx.y << 7;
    const int bn = blockIdx.x << 7;
    const int z = OPROJ ? 3 : (int)blockIdx.z;

    const float* bias = OPROJ ? b0p : (z == 0) ? b0p : (z == 1) ? b1p : b2p;

    const int wm = (wid >> 2) * 64;
    const int wn = (wid & 3) * 32;

    const __nv_bfloat16* srcs[4];
    srcs[0] = Ah + (size_t)bm * EMB;
    srcs[1] = Al + (size_t)bm * EMB;
    srcs[2] = g_wh + (size_t)z * WSZ + (size_t)bn * EMB;
    srcs[3] = g_wl + (size_t)z * WSZ + (size_t)bn * EMB;
    const uint32_t sbase = smem_u32(dyn);

    // cp.async one K-chunk (32 cols) of all 4 tiles into stage c%3
    auto prefetch = [&](int c) {
        const uint32_t st = sbase + (uint32_t)(c % 3) * 40960u;
        const int kc = c * 32;
#pragma unroll
        for (int t = 0; t < 4; t++) {
#pragma unroll
            for (int j = 0; j < 2; j++) {
                int idx = tid + j * 256;          // 0..511
                int r = idx >> 2, g = idx & 3;
                cpa16(st + (uint32_t)(t * 10240 + r * 80 + g * 16),
                      srcs[t] + (size_t)r * EMB + kc + g * 8);
            }
        }
    };

    float acc[4][4][4];
#pragma unroll
    for (int i = 0; i < 4; i++)
#pragma unroll
        for (int j = 0; j < 4; j++)
#pragma unroll
            for (int t = 0; t < 4; t++) acc[i][j][t] = 0.f;

    prefetch(0); CP_COMMIT();
    prefetch(1); CP_COMMIT();

    for (int c = 0; c < 32; c++) {
        if (c + 2 < 32) CP_WAIT1(); else CP_WAIT0();
        __syncthreads();
        if (c + 2 < 32) { prefetch(c + 2); CP_COMMIT(); }

        const uint32_t sb = sbase + (uint32_t)(c % 3) * 40960u;
#pragma unroll
        for (int ks = 0; ks < 2; ks++) {
            uint32_t ah[4][4], al[4][4];
#pragma unroll
            for (int mt = 0; mt < 4; mt++) {
                uint32_t ad = sb + (uint32_t)((wm + mt * 16 + (lane & 15)) * 80
                                              + (ks * 16 + (lane >> 4) * 8) * 2);
                ldsm4(ah[mt], ad);
                ldsm4(al[mt], ad + 10240);
            }
            uint32_t bh[4][2], bl[4][2];
#pragma unroll
            for (int u = 0; u < 2; u++) {
                uint32_t bd = sb + 20480u
                    + (uint32_t)((wn + u * 16 + (lane & 7) + ((lane >> 4) & 1) * 8) * 80
                                 + (ks * 16 + ((lane >> 3) & 1) * 8) * 2);
                uint32_t r4[4];
                ldsm4(r4, bd);
                bh[2 * u][0] = r4[0]; bh[2 * u][1] = r4[1];
                bh[2 * u + 1][0] = r4[2]; bh[2 * u + 1][1] = r4[3];
                ldsm4(r4, bd + 10240);
                bl[2 * u][0] = r4[0]; bl[2 * u][1] = r4[1];
                bl[2 * u + 1][0] = r4[2]; bl[2 * u + 1][1] = r4[3];
            }
#pragma unroll
            for (int mt = 0; mt < 4; mt++)
#pragma unroll
                for (int nt = 0; nt < 4; nt++) {
                    mma_bf16(acc[mt][nt], ah[mt], bh[nt][0], bh[nt][1]);
                    mma_bf16(acc[mt][nt], ah[mt], bl[nt][0], bl[nt][1]);
                    mma_bf16(acc[mt][nt], al[mt], bh[nt][0], bh[nt][1]);
                }
        }
        __syncthreads();
    }

    // ---- epilogue ----
#pragma unroll
    for (int mt = 0; mt < 4; mt++)
#pragma unroll
        for (int nt = 0; nt < 4; nt++)
#pragma unroll
            for (int half = 0; half < 2; half++) {
                const int m = bm + wm + mt * 16 + (lane >> 2) + half * 8;
                const int n = bn + wn + nt * 8 + (lane & 3) * 2;
                float v0 = acc[mt][nt][half * 2 + 0] + bias[n];
                float v1 = acc[mt][nt][half * 2 + 1] + bias[n + 1];
                if (OPROJ) {
                    *(float2*)(Oout + (size_t)m * EMB + n) = make_float2(v0, v1);
                } else if (z == 0) {
                    const int hh = n >> 6, d = n & 63;
                    const int bq = m >> 11, s = m & 2047;
                    *(float2*)(&g_q[(((size_t)bq * HH + hh) * SSEQ + s) * DH + d]) =
                        make_float2(v0, v1);
                } else {
                    const int bhd = (m >> 11) * HH + (n >> 6);
                    const int d = n & 63, s = m & 2047;
                    uint32_t h0 = packbf(v0, v1);
                    uint32_t l0 = packbf(v0 - bflo(h0), v1 - bfhi(h0));
                    if (z == 1) {
                        const size_t base = ((size_t)bhd * SSEQ + s) * 128 + d;
                        *(uint32_t*)&g_kx_h[base] = h0;
                        *(uint32_t*)&g_kx_l[base] = l0;
                        float t0 = tanhf(v0), t1 = tanhf(v1);
                        uint32_t th = packbf(t0, t1);
                        uint32_t tl = packbf(t0 - bflo(th), t1 - bfhi(th));
                        *(uint32_t*)&g_kx_h[base + 64] = th;
                        *(uint32_t*)&g_kx_l[base + 64] = tl;
                    } else {
                        const size_t base = ((size_t)bhd * SSEQ + s) * 64 + d;
                        *(uint32_t*)&g_vx_h[base] = h0;
                        *(uint32_t*)&g_vx_l[base] = l0;
                    }
                }
            }
}

// ============================================================================
// Flash attention (HMMA): score = Q'(128-deep) . K'^T, online softmax per
// 16-row warp (stats in registers, P repacked accum->A-frag, no smem P).
// Q' = [Q*0.125 | lam*(tanh(Q)@J)] built in prologue (fp32), split hi/lo bf16.
// Epilogue writes ctx as bf16 hi/lo (pre-split for the O projection).
// ============================================================================
#define F_QH   0
#define F_QL   34816
#define F_STG  69632
#define F_SSZ  53248
#define F_KL   17408
#define F_VH   34816
#define F_VL   44032
#define F_TOT  176128

__global__ __launch_bounds__(256, 1)
void flash_mma(const float* __restrict__ Jg, const float* __restrict__ lam_ptr)
{
    extern __shared__ __align__(16) char dyn[];
    const int tid = threadIdx.x;
    const int lane = tid & 31;
    const int w = tid >> 5;
    const int qt = blockIdx.x;       // 0..15
    const int bh = blockIdx.y;       // 0..31
    const int h = bh & (HH - 1);
    const int b = bh >> 4;
    const float lam = *lam_ptr;
    const uint32_t sb0 = smem_u32(dyn);

    float* QS = (float*)(dyn + F_STG);   // 128 x 132 fp32
    float* TQ = (float*)(dyn);           // 128 x 68  fp32
    float* JS = (float*)(dyn + 34816);   // 64 x 68   fp32

    // ---- prologue: Q raw + tanh(Q), J ----
    const float* Qb = g_q + ((size_t)bh * SSEQ + (size_t)qt * 128) * DH;
#pragma unroll
    for (int it = 0; it < 8; it++) {
        int idx = tid + it * 256;
        int r = idx >> 4, c = (idx & 15) << 2;
        float4 v = *(const float4*)(Qb + r * DH + c);
        QS[r * 132 + c + 0] = v.x; QS[r * 132 + c + 1] = v.y;
        QS[r * 132 + c + 2] = v.z; QS[r * 132 + c + 3] = v.w;
        TQ[r * 68 + c + 0] = tanhf(v.x); TQ[r * 68 + c + 1] = tanhf(v.y);
        TQ[r * 68 + c + 2] = tanhf(v.z); TQ[r * 68 + c + 3] = tanhf(v.w);
    }
    const float* Jb = Jg + (size_t)h * DH * DH;
#pragma unroll
    for (int it = 0; it < 4; it++) {
        int idx = tid + it * 256;
        int r = idx >> 4, c = (idx & 15) << 2;
        float4 v = *(const float4*)(Jb + r * DH + c);
        JS[r * 68 + c + 0] = v.x; JS[r * 68 + c + 1] = v.y;
        JS[r * 68 + c + 2] = v.z; JS[r * 68 + c + 3] = v.w;
    }
    __syncthreads();

    // ---- QJ = tanh(Q) @ J (scalar fp32, tiny) ----
    {
        const int tx = tid & 7, ty = tid >> 3;
        float a2[4][8];
#pragma unroll
        for (int i = 0; i < 4; i++)
#pragma unroll
            for (int j = 0; j < 8; j++) a2[i][j] = 0.f;
#pragma unroll 4
        for (int d0 = 0; d0 < 64; d0 += 4) {
            float a[4][4];
#pragma unroll
            for (int i = 0; i < 4; i++) {
                float4 t = *(const float4*)&TQ[(ty * 4 + i) * 68 + d0];
                a[i][0] = t.x; a[i][1] = t.y; a[i][2] = t.z; a[i][3] = t.w;
            }
#pragma unroll
            for (int dd = 0; dd < 4; dd++) {
                float bb[8];
#pragma unroll
                for (int j = 0; j < 8; j++) bb[j] = JS[(d0 + dd) * 68 + tx + j * 8];
#pragma unroll
                for (int i = 0; i < 4; i++)
#pragma unroll
                    for (int j = 0; j < 8; j++) a2[i][j] += a[i][dd] * bb[j];
            }
        }
#pragma unroll
        for (int i = 0; i < 4; i++) {
            int r = ty * 4 + i;
#pragma unroll
            for (int j = 0; j < 8; j++) {
                int c = tx + j * 8;
                QS[r * 132 + 64 + c] = lam * a2[i][j];
                QS[r * 132 + c] *= 0.125f;
            }
        }
    }
    __syncthreads();

    // ---- convert QS fp32 -> Qh/Ql bf16 tiles (overwrites TQ/JS) ----
#pragma unroll
    for (int it = 0; it < 16; it++) {
        int idx = tid + it * 256;
        int r = idx >> 5, g = idx & 31;
        float4 v = *(const float4*)&QS[r * 132 + g * 4];
        uint32_t h0, h1, l0, l1;
        split4(v, h0, h1, l0, l1);
        *(uint2*)(dyn + F_QH + r * 272 + g * 8) = make_uint2(h0, h1);
        *(uint2*)(dyn + F_QL + r * 272 + g * 8) = make_uint2(l0, l1);
    }
    __syncthreads();

    const __nv_bfloat16* KHg = g_kx_h + (size_t)bh * SSEQ * 128;
    const __nv_bfloat16* KLg = g_kx_l + (size_t)bh * SSEQ * 128;
    const __nv_bfloat16* VHg = g_vx_h + (size_t)bh * SSEQ * 64;
    const __nv_bfloat16* VLg = g_vx_l + (size_t)bh * SSEQ * 64;

    auto prefetch = [&](int kt) {
        uint32_t d = sb0 + F_STG + (uint32_t)(kt & 1) * F_SSZ;
        const int s0 = kt * 64;
#pragma unroll
        for (int it = 0; it < 4; it++) {
            int idx = tid + it * 256;
            int r = idx >> 4, g = idx & 15;
            cpa16(d +        r * 272 + g * 16, KHg + (size_t)(s0 + r) * 128 + g * 8);
            cpa16(d + F_KL + r * 272 + g * 16, KLg + (size_t)(s0 + r) * 128 + g * 8);
        }
#pragma unroll
        for (int it = 0; it < 2; it++) {
            int idx = tid + it * 256;
            int r = idx >> 3, g = idx & 7;
            cpa16(d + F_VH + r * 144 + g * 16, VHg + (size_t)(s0 + r) * 64 + g * 8);
            cpa16(d + F_VL + r * 144 + g * 16, VLg + (size_t)(s0 + r) * 64 + g * 8);
        }
    };

    prefetch(0);
    CP_COMMIT();

    // ---- preload Q fragments ----
    uint32_t qh[8][4], ql[8][4];
#pragma unroll
    for (int ks = 0; ks < 8; ks++) {
        uint32_t ad = sb0 + F_QH + (uint32_t)((w * 16 + (lane & 15)) * 272
                                              + (ks * 16 + (lane >> 4) * 8) * 2);
        ldsm4(qh[ks], ad);
        ldsm4(ql[ks], ad + F_QL);
    }

    float o[8][4];
#pragma unroll
    for (int i = 0; i < 8; i++)
#pragma unroll
        for (int t = 0; t < 4; t++) o[i][t] = 0.f;
    float mrow[2] = { -1e30f, -1e30f };
    float lsum[2] = { 0.f, 0.f };

    for (int kt = 0; kt < SSEQ / 64; kt++) {
        if (kt + 1 < SSEQ / 64) {
            prefetch(kt + 1);
            CP_COMMIT();
            CP_WAIT1();
        } else {
            CP_WAIT0();
        }
        __syncthreads();

        const uint32_t sb = sb0 + F_STG + (uint32_t)(kt & 1) * F_SSZ;

        float s[8][4];
#pragma unroll
        for (int i = 0; i < 8; i++)
#pragma unroll
            for (int t = 0; t < 4; t++) s[i][t] = 0.f;
#pragma unroll
        for (int ks = 0; ks < 8; ks++) {
#pragma unroll
            for (int u = 0; u < 4; u++) {
                uint32_t bd = sb + (uint32_t)((u * 16 + (lane & 7) + ((lane >> 4) & 1) * 8) * 272
                                              + (ks * 16 + ((lane >> 3) & 1) * 8) * 2);
                uint32_t kh4[4], kl4[4];
                ldsm4(kh4, bd);
                ldsm4(kl4, bd + F_KL);
                mma_bf16(s[2 * u],     qh[ks], kh4[0], kh4[1]);
                mma_bf16(s[2 * u],     qh[ks], kl4[0], kl4[1]);
                mma_bf16(s[2 * u],     ql[ks], kh4[0], kh4[1]);
                mma_bf16(s[2 * u + 1], qh[ks], kh4[2], kh4[3]);
                mma_bf16(s[2 * u + 1], qh[ks], kl4[2], kl4[3]);
                mma_bf16(s[2 * u + 1], ql[ks], kh4[2], kh4[3]);
            }
        }

#pragma unroll
        for (int rr = 0; rr < 2; rr++) {
            float rm = -1e30f;
#pragma unroll
            for (int nt = 0; nt < 8; nt++) {
                rm = fmaxf(rm, s[nt][rr * 2 + 0]);
                rm = fmaxf(rm, s[nt][rr * 2 + 1]);
            }
            rm = fmaxf(rm, __shfl_xor_sync(0xffffffffu, rm, 1));
            rm = fmaxf(rm, __shfl_xor_sync(0xffffffffu, rm, 2));
            const float mnew = fmaxf(mrow[rr], rm);
            const float alpha = __expf(mrow[rr] - mnew);
            mrow[rr] = mnew;
            float rs = 0.f;
#pragma unroll
            for (int nt = 0; nt < 8; nt++) {
                float p0 = __expf(s[nt][rr * 2 + 0] - mnew);
                float p1 = __expf(s[nt][rr * 2 + 1] - mnew);
                s[nt][rr * 2 + 0] = p0;
                s[nt][rr * 2 + 1] = p1;
                rs += p0 + p1;
            }
            rs += __shfl_xor_sync(0xffffffffu, rs, 1);
            rs += __shfl_xor_sync(0xffffffffu, rs, 2);
            lsum[rr] = lsum[rr] * alpha + rs;
#pragma unroll
            for (int nt = 0; nt < 8; nt++) {
                o[nt][rr * 2 + 0] *= alpha;
                o[nt][rr * 2 + 1] *= alpha;
            }
        }

#pragma unroll
        for (int t = 0; t < 4; t++) {
            uint32_t ph[4], pl[4];
            ph[0] = packbf(s[2 * t][0], s[2 * t][1]);
            pl[0] = packbf(s[2 * t][0] - bflo(ph[0]), s[2 * t][1] - bfhi(ph[0]));
            ph[1] = packbf(s[2 * t][2], s[2 * t][3]);
            pl[1] = packbf(s[2 * t][2] - bflo(ph[1]), s[2 * t][3] - bfhi(ph[1]));
            ph[2] = packbf(s[2 * t + 1][0], s[2 * t + 1][1]);
            pl[2] = packbf(s[2 * t + 1][0] - bflo(ph[2]), s[2 * t + 1][1] - bfhi(ph[2]));
            ph[3] = packbf(s[2 * t + 1][2], s[2 * t + 1][3]);
            pl[3] = packbf(s[2 * t + 1][2] - bflo(ph[3]), s[2 * t + 1][3] - bfhi(ph[3]));
#pragma unroll
            for (int u = 0; u < 4; u++) {
                uint32_t vd = sb + F_VH
                    + (uint32_t)((t * 16 + (lane & 7) + ((lane >> 3) & 1) * 8) * 144
                                 + (u * 16 + ((lane >> 4) & 1) * 8) * 2);
                uint32_t vh4[4], vl4[4];
                ldsm4t(vh4, vd);
                ldsm4t(vl4, vd + (F_VL - F_VH));
                mma_bf16(o[2 * u],     ph, vh4[0], vh4[1]);
                mma_bf16(o[2 * u],     ph, vl4[0], vl4[1]);
                mma_bf16(o[2 * u],     pl, vh4[0], vh4[1]);
                mma_bf16(o[2 * u + 1], ph, vh4[2], vh4[3]);
                mma_bf16(o[2 * u + 1], ph, vl4[2], vl4[3]);
                mma_bf16(o[2 * u + 1], pl, vh4[2], vh4[3]);
            }
        }
        __syncthreads();
    }

    // ---- epilogue: ctx (bf16 hi/lo) = O / l ----
    const float inv0 = 1.f / lsum[0];
    const float inv1 = 1.f / lsum[1];
    const int r0 = qt * 128 + w * 16 + (lane >> 2);
#pragma unroll
    for (int nt = 0; nt < 8; nt++) {
        const int d = h * DH + nt * 8 + (lane & 3) * 2;
        {
            const size_t i0 = ((size_t)b * SSEQ + r0) * EMB + d;
            float v0 = o[nt][0] * inv0, v1 = o[nt][1] * inv0;
            uint32_t hh = packbf(v0, v1);
            uint32_t ll = packbf(v0 - bflo(hh), v1 - bfhi(hh));
            *(uint32_t*)&g_ctx_h[i0] = hh;
            *(uint32_t*)&g_ctx_l[i0] = ll;
        }
        {
            const size_t i1 = ((size_t)b * SSEQ + r0 + 8) * EMB + d;
            float v0 = o[nt][2] * inv1, v1 = o[nt][3] * inv1;
            uint32_t hh = packbf(v0, v1);
            uint32_t ll = packbf(v0 - bflo(hh), v1 - bfhi(hh));
            *(uint32_t*)&g_ctx_h[i1] = hh;
            *(uint32_t*)&g_ctx_l[i1] = ll;
        }
    }
}

// ============================================================================
extern "C" void kernel_launch(void* const* d_in, const int* in_sizes, int n_in,
                              void* d_out, int out_size)
{
    const float* x   = (const float*)d_in[0];
    const float* Wq  = (const float*)d_in[1];
    const float* bq  = (const float*)d_in[2];
    const float* Wk  = (const float*)d_in[3];
    const float* bk  = (const float*)d_in[4];
    const float* Wv  = (const float*)d_in[5];
    const float* bv  = (const float*)d_in[6];
    const float* Wo  = (const float*)d_in[7];
    const float* bo  = (const float*)d_in[8];
    const float* J   = (const float*)d_in[9];
    const float* lam = (const float*)d_in[10];
    float* out = (float*)d_out;
    (void)in_sizes; (void)n_in; (void)out_size;

    __nv_bfloat16 *xh, *xl, *wh, *wl, *ch, *cl;
    cudaGetSymbolAddress((void**)&xh, g_xh);
    cudaGetSymbolAddress((void**)&xl, g_xl);
    cudaGetSymbolAddress((void**)&wh, g_wh);
    cudaGetSymbolAddress((void**)&wl, g_wl);
    cudaGetSymbolAddress((void**)&ch, g_ctx_h);
    cudaGetSymbolAddress((void**)&cl, g_ctx_l);

    // pre-split all GEMM operands to bf16 hi/lo
    conv_split<<<(MTOT * EMB / 4) / 256, 256>>>(x, xh, xl, MTOT * EMB / 4);
    conv_split<<<(EMB * EMB / 4) / 256, 256>>>(Wq, wh + 0 * WSZ, wl + 0 * WSZ, EMB * EMB / 4);
    conv_split<<<(EMB * EMB / 4) / 256, 256>>>(Wk, wh + 1 * WSZ, wl + 1 * WSZ, EMB * EMB / 4);
    conv_split<<<(EMB * EMB / 4) / 256, 256>>>(Wv, wh + 2 * WSZ, wl + 2 * WSZ, EMB * EMB / 4);
    conv_split<<<(EMB * EMB / 4) / 256, 256>>>(Wo, wh + 3 * WSZ, wl + 3 * WSZ, EMB * EMB / 4);

    const int gsmem = 3 * 40960;   // 120KB
    cudaFuncSetAttribute(gemm_bf16<0>, cudaFuncAttributeMaxDynamicSharedMemorySize, gsmem);
    cudaFuncSetAttribute(gemm_bf16<1>, cudaFuncAttributeMaxDynamicSharedMemorySize, gsmem);
    cudaFuncSetAttribute(flash_mma, cudaFuncAttributeMaxDynamicSharedMemorySize, F_TOT);

    // fused QKV projections; z=0 Q, z=1 K (ext + tanh), z=2 V (ext)
    gemm_bf16<0><<<dim3(EMB / 128, MTOT / 128, 3), 256, gsmem>>>(
        xh, xl, bq, bk, bv, nullptr);

    flash_mma<<<dim3(SSEQ / 128, BB * HH), 256, F_TOT>>>(J, lam);

    // output projection (weights slot 3)
    gemm_bf16<1><<<dim3(EMB / 128, MTOT / 128, 1), 256, gsmem>>>(
        ch, cl, bo, nullptr, nullptr, out);
}

// round 16
// speedup vs baseline: 1.0364x; 1.0364x over previous
#include <cuda_runtime.h>
#include <cuda_bf16.h>
#include <cstdint>
#include <math.h>

#define BB   2
#define HH   16
#define SSEQ 2048
#define DH   64
#define EMB  1024
#define MTOT (BB * SSEQ)   // 4096
#define WSZ  ((size_t)EMB * EMB)

// ---- scratch (no allocation allowed) ----
__device__ float g_q[(size_t)BB * HH * SSEQ * DH];            // [B,H,S,D] fp32
__device__ __nv_bfloat16 g_xh[(size_t)MTOT * EMB];
__device__ __nv_bfloat16 g_xl[(size_t)MTOT * EMB];
__device__ __nv_bfloat16 g_wh[4 * WSZ];                        // Wq,Wk,Wv,Wo
__device__ __nv_bfloat16 g_wl[4 * WSZ];
__device__ __nv_bfloat16 g_ctx_h[(size_t)MTOT * EMB];          // attn output
__device__ __nv_bfloat16 g_ctx_l[(size_t)MTOT * EMB];
// K' = [K | tanh(K)] bf16 hi/lo split, [bh][s][128]
__device__ __nv_bfloat16 g_kx_h[(size_t)BB * HH * SSEQ * 128];
__device__ __nv_bfloat16 g_kx_l[(size_t)BB * HH * SSEQ * 128];
// V bf16 hi/lo split, [bh][s][64]
__device__ __nv_bfloat16 g_vx_h[(size_t)BB * HH * SSEQ * 64];
__device__ __nv_bfloat16 g_vx_l[(size_t)BB * HH * SSEQ * 64];

// ============================================================================
// helpers
// ============================================================================
__device__ __forceinline__ uint32_t smem_u32(const void* p) {
    uint32_t a;
    asm("{ .reg .u64 t; cvta.to.shared.u64 t, %1; cvt.u32.u64 %0, t; }" : "=r"(a) : "l"(p));
    return a;
}
__device__ __forceinline__ void ldsm4(uint32_t* r, uint32_t addr) {
    asm volatile("ldmatrix.sync.aligned.m8n8.x4.shared.b16 {%0,%1,%2,%3}, [%4];"
        : "=r"(r[0]), "=r"(r[1]), "=r"(r[2]), "=r"(r[3]) : "r"(addr));
}
__device__ __forceinline__ void ldsm4t(uint32_t* r, uint32_t addr) {
    asm volatile("ldmatrix.sync.aligned.m8n8.x4.trans.shared.b16 {%0,%1,%2,%3}, [%4];"
        : "=r"(r[0]), "=r"(r[1]), "=r"(r[2]), "=r"(r[3]) : "r"(addr));
}
// D += A(bf16 m16k16) * B(bf16 k16n8), fp32 accum
__device__ __forceinline__ void mma_bf16(float* d, const uint32_t* a, uint32_t b0, uint32_t b1) {
    asm volatile("mma.sync.aligned.m16n8k16.row.col.f32.bf16.bf16.f32 "
        "{%0,%1,%2,%3}, {%4,%5,%6,%7}, {%8,%9}, {%0,%1,%2,%3};"
        : "+f"(d[0]), "+f"(d[1]), "+f"(d[2]), "+f"(d[3])
        : "r"(a[0]), "r"(a[1]), "r"(a[2]), "r"(a[3]), "r"(b0), "r"(b1));
}
__device__ __forceinline__ uint32_t packbf(float lo, float hi) {
    uint32_t r;
    asm("cvt.rn.bf16x2.f32 %0, %1, %2;" : "=r"(r) : "f"(hi), "f"(lo));
    return r;
}
__device__ __forceinline__ float bflo(uint32_t u) { return __uint_as_float(u << 16); }
__device__ __forceinline__ float bfhi(uint32_t u) { return __uint_as_float(u & 0xffff0000u); }

__device__ __forceinline__ void split4(float4 v, uint32_t& h0, uint32_t& h1,
                                       uint32_t& l0, uint32_t& l1) {
    h0 = packbf(v.x, v.y);
    h1 = packbf(v.z, v.w);
    l0 = packbf(v.x - bflo(h0), v.y - bfhi(h0));
    l1 = packbf(v.z - bflo(h1), v.w - bfhi(h1));
}

__device__ __forceinline__ void cpa16(uint32_t dst, const void* src) {
    asm volatile("cp.async.cg.shared.global [%0], [%1], 16;" :: "r"(dst), "l"(src));
}
#define CP_COMMIT() asm volatile("cp.async.commit_group;" ::: "memory")
#define CP_WAIT1()  asm volatile("cp.async.wait_group 1;" ::: "memory")
#define CP_WAIT0()  asm volatile("cp.async.wait_group 0;" ::: "memory")

// ============================================================================
// pre-pass: fp32 -> bf16 hi/lo residual split
// ============================================================================
__global__ __launch_bounds__(256)
void conv_split(const float* __restrict__ src, __nv_bfloat16* __restrict__ dh,
                __nv_bfloat16* __restrict__ dl, int n4)
{
    int i = blockIdx.x * 256 + threadIdx.x;
    if (i < n4) {
        float4 v = ((const float4*)src)[i];
        uint32_t h0, h1, l0, l1;
        split4(v, h0, h1, l0, l1);
        ((uint2*)dh)[i] = make_uint2(h0, h1);
        ((uint2*)dl)[i] = make_uint2(l0, l1);
    }
}

// ============================================================================
// HMMA GEMM on pre-split bf16 operands: C = A @ W^T + bias.
// CTA tile 128x128, K-chunk 32, 3-stage cp.async pipeline, 8 warps (2Mx4N),
// warp tile 64x32. MMA stream reordered into 3 passes of 16 independent MMAs
// (accumulator reuse distance 16 — no RAW issue stalls).
// ============================================================================
template <int OPROJ>
__global__ __launch_bounds__(256, 1)
void gemm_bf16(const __nv_bfloat16* __restrict__ Ah,
               const __nv_bfloat16* __restrict__ Al,
               const float* __restrict__ b0p, const float* __restrict__ b1p,
               const float* __restrict__ b2p, float* __restrict__ Oout)
{
    extern __shared__ __align__(16) char dyn[];
    const int tid = threadIdx.x;
    const int lane = tid & 31;
    const int wid = tid >> 5;
    const int bm = blockIdx.y << 7;
    const int bn = blockIdx.x << 7;
    const int z = OPROJ ? 3 : (int)blockIdx.z;

    const float* bias = OPROJ ? b0p : (z == 0) ? b0p : (z == 1) ? b1p : b2p;

    const int wm = (wid >> 2) * 64;
    const int wn = (wid & 3) * 32;

    const __nv_bfloat16* srcs[4];
    srcs[0] = Ah + (size_t)bm * EMB;
    srcs[1] = Al + (size_t)bm * EMB;
    srcs[2] = g_wh + (size_t)z * WSZ + (size_t)bn * EMB;
    srcs[3] = g_wl + (size_t)z * WSZ + (size_t)bn * EMB;
    const uint32_t sbase = smem_u32(dyn);

    auto prefetch = [&](int c) {
        const uint32_t st = sbase + (uint32_t)(c % 3) * 40960u;
        const int kc = c * 32;
#pragma unroll
        for (int t = 0; t < 4; t++) {
#pragma unroll
            for (int j = 0; j < 2; j++) {
                int idx = tid + j * 256;
                int r = idx >> 2, g = idx & 3;
                cpa16(st + (uint32_t)(t * 10240 + r * 80 + g * 16),
                      srcs[t] + (size_t)r * EMB + kc + g * 8);
            }
        }
    };

    float acc[4][4][4];
#pragma unroll
    for (int i = 0; i < 4; i++)
#pragma unroll
        for (int j = 0; j < 4; j++)
#pragma unroll
            for (int t = 0; t < 4; t++) acc[i][j][t] = 0.f;

    prefetch(0); CP_COMMIT();
    prefetch(1); CP_COMMIT();

    for (int c = 0; c < 32; c++) {
        if (c + 2 < 32) CP_WAIT1(); else CP_WAIT0();
        __syncthreads();
        if (c + 2 < 32) { prefetch(c + 2); CP_COMMIT(); }

        const uint32_t sb = sbase + (uint32_t)(c % 3) * 40960u;
#pragma unroll
        for (int ks = 0; ks < 2; ks++) {
            uint32_t ah[4][4], al[4][4];
#pragma unroll
            for (int mt = 0; mt < 4; mt++) {
                uint32_t ad = sb + (uint32_t)((wm + mt * 16 + (lane & 15)) * 80
                                              + (ks * 16 + (lane >> 4) * 8) * 2);
                ldsm4(ah[mt], ad);
                ldsm4(al[mt], ad + 10240);
            }
            uint32_t bh[4][2], bl[4][2];
#pragma unroll
            for (int u = 0; u < 2; u++) {
                uint32_t bd = sb + 20480u
                    + (uint32_t)((wn + u * 16 + (lane & 7) + ((lane >> 4) & 1) * 8) * 80
                                 + (ks * 16 + ((lane >> 3) & 1) * 8) * 2);
                uint32_t r4[4];
                ldsm4(r4, bd);
                bh[2 * u][0] = r4[0]; bh[2 * u][1] = r4[1];
                bh[2 * u + 1][0] = r4[2]; bh[2 * u + 1][1] = r4[3];
                ldsm4(r4, bd + 10240);
                bl[2 * u][0] = r4[0]; bl[2 * u][1] = r4[1];
                bl[2 * u + 1][0] = r4[2]; bl[2 * u + 1][1] = r4[3];
            }
            // pass 1: Ah*Bh (16 independent MMAs)
#pragma unroll
            for (int mt = 0; mt < 4; mt++)
#pragma unroll
                for (int nt = 0; nt < 4; nt++)
                    mma_bf16(acc[mt][nt], ah[mt], bh[nt][0], bh[nt][1]);
            // pass 2: Ah*Bl
#pragma unroll
            for (int mt = 0; mt < 4; mt++)
#pragma unroll
                for (int nt = 0; nt < 4; nt++)
                    mma_bf16(acc[mt][nt], ah[mt], bl[nt][0], bl[nt][1]);
            // pass 3: Al*Bh
#pragma unroll
            for (int mt = 0; mt < 4; mt++)
#pragma unroll
                for (int nt = 0; nt < 4; nt++)
                    mma_bf16(acc[mt][nt], al[mt], bh[nt][0], bh[nt][1]);
        }
        __syncthreads();
    }

    // ---- epilogue ----
#pragma unroll
    for (int mt = 0; mt < 4; mt++)
#pragma unroll
        for (int nt = 0; nt < 4; nt++)
#pragma unroll
            for (int half = 0; half < 2; half++) {
                const int m = bm + wm + mt * 16 + (lane >> 2) + half * 8;
                const int n = bn + wn + nt * 8 + (lane & 3) * 2;
                float v0 = acc[mt][nt][half * 2 + 0] + bias[n];
                float v1 = acc[mt][nt][half * 2 + 1] + bias[n + 1];
                if (OPROJ) {
                    *(float2*)(Oout + (size_t)m * EMB + n) = make_float2(v0, v1);
                } else if (z == 0) {
                    const int hh = n >> 6, d = n & 63;
                    const int bq = m >> 11, s = m & 2047;
                    *(float2*)(&g_q[(((size_t)bq * HH + hh) * SSEQ + s) * DH + d]) =
                        make_float2(v0, v1);
                } else {
                    const int bhd = (m >> 11) * HH + (n >> 6);
                    const int d = n & 63, s = m & 2047;
                    uint32_t h0 = packbf(v0, v1);
                    uint32_t l0 = packbf(v0 - bflo(h0), v1 - bfhi(h0));
                    if (z == 1) {
                        const size_t base = ((size_t)bhd * SSEQ + s) * 128 + d;
                        *(uint32_t*)&g_kx_h[base] = h0;
                        *(uint32_t*)&g_kx_l[base] = l0;
                        float t0 = tanhf(v0), t1 = tanhf(v1);
                        uint32_t th = packbf(t0, t1);
                        uint32_t tl = packbf(t0 - bflo(th), t1 - bfhi(th));
                        *(uint32_t*)&g_kx_h[base + 64] = th;
                        *(uint32_t*)&g_kx_l[base + 64] = tl;
                    } else {
                        const size_t base = ((size_t)bhd * SSEQ + s) * 64 + d;
                        *(uint32_t*)&g_vx_h[base] = h0;
                        *(uint32_t*)&g_vx_l[base] = l0;
                    }
                }
            }
}

// ============================================================================
// Flash attention (HMMA), MMA streams reordered into independent passes.
// Score ks 0..3 (raw-Q half): 3 products; ks 4..7 (lam*QJ half): 2 products
// (QJ-lo cross dropped; |err| ~ 3e-4 absolute on scores, within 1e-3 gate).
// ============================================================================
#define F_QH   0
#define F_QL   34816
#define F_STG  69632
#define F_SSZ  53248
#define F_KL   17408
#define F_VH   34816
#define F_VL   44032
#define F_TOT  176128

__global__ __launch_bounds__(256, 1)
void flash_mma(const float* __restrict__ Jg, const float* __restrict__ lam_ptr)
{
    extern __shared__ __align__(16) char dyn[];
    const int tid = threadIdx.x;
    const int lane = tid & 31;
    const int w = tid >> 5;
    const int qt = blockIdx.x;
    const int bh = blockIdx.y;
    const int h = bh & (HH - 1);
    const int b = bh >> 4;
    const float lam = *lam_ptr;
    const uint32_t sb0 = smem_u32(dyn);

    float* QS = (float*)(dyn + F_STG);   // 128 x 132 fp32
    float* TQ = (float*)(dyn);           // 128 x 68  fp32
    float* JS = (float*)(dyn + 34816);   // 64 x 68   fp32

    // ---- prologue: Q raw + tanh(Q), J ----
    const float* Qb = g_q + ((size_t)bh * SSEQ + (size_t)qt * 128) * DH;
#pragma unroll
    for (int it = 0; it < 8; it++) {
        int idx = tid + it * 256;
        int r = idx >> 4, c = (idx & 15) << 2;
        float4 v = *(const float4*)(Qb + r * DH + c);
        QS[r * 132 + c + 0] = v.x; QS[r * 132 + c + 1] = v.y;
        QS[r * 132 + c + 2] = v.z; QS[r * 132 + c + 3] = v.w;
        TQ[r * 68 + c + 0] = tanhf(v.x); TQ[r * 68 + c + 1] = tanhf(v.y);
        TQ[r * 68 + c + 2] = tanhf(v.z); TQ[r * 68 + c + 3] = tanhf(v.w);
    }
    const float* Jb = Jg + (size_t)h * DH * DH;
#pragma unroll
    for (int it = 0; it < 4; it++) {
        int idx = tid + it * 256;
        int r = idx >> 4, c = (idx & 15) << 2;
        float4 v = *(const float4*)(Jb + r * DH + c);
        JS[r * 68 + c + 0] = v.x; JS[r * 68 + c + 1] = v.y;
        JS[r * 68 + c + 2] = v.z; JS[r * 68 + c + 3] = v.w;
    }
    __syncthreads();

    // ---- QJ = tanh(Q) @ J ----
    {
        const int tx = tid & 7, ty = tid >> 3;
        float a2[4][8];
#pragma unroll
        for (int i = 0; i < 4; i++)
#pragma unroll
            for (int j = 0; j < 8; j++) a2[i][j] = 0.f;
#pragma unroll 4
        for (int d0 = 0; d0 < 64; d0 += 4) {
            float a[4][4];
#pragma unroll
            for (int i = 0; i < 4; i++) {
                float4 t = *(const float4*)&TQ[(ty * 4 + i) * 68 + d0];
                a[i][0] = t.x; a[i][1] = t.y; a[i][2] = t.z; a[i][3] = t.w;
            }
#pragma unroll
            for (int dd = 0; dd < 4; dd++) {
                float bb[8];
#pragma unroll
                for (int j = 0; j < 8; j++) bb[j] = JS[(d0 + dd) * 68 + tx + j * 8];
#pragma unroll
                for (int i = 0; i < 4; i++)
#pragma unroll
                    for (int j = 0; j < 8; j++) a2[i][j] += a[i][dd] * bb[j];
            }
        }
#pragma unroll
        for (int i = 0; i < 4; i++) {
            int r = ty * 4 + i;
#pragma unroll
            for (int j = 0; j < 8; j++) {
                int c = tx + j * 8;
                QS[r * 132 + 64 + c] = lam * a2[i][j];
                QS[r * 132 + c] *= 0.125f;
            }
        }
    }
    __syncthreads();

    // ---- convert QS fp32 -> Qh/Ql bf16 tiles ----
#pragma unroll
    for (int it = 0; it < 16; it++) {
        int idx = tid + it * 256;
        int r = idx >> 5, g = idx & 31;
        float4 v = *(const float4*)&QS[r * 132 + g * 4];
        uint32_t h0, h1, l0, l1;
        split4(v, h0, h1, l0, l1);
        *(uint2*)(dyn + F_QH + r * 272 + g * 8) = make_uint2(h0, h1);
        *(uint2*)(dyn + F_QL + r * 272 + g * 8) = make_uint2(l0, l1);
    }
    __syncthreads();

    const __nv_bfloat16* KHg = g_kx_h + (size_t)bh * SSEQ * 128;
    const __nv_bfloat16* KLg = g_kx_l + (size_t)bh * SSEQ * 128;
    const __nv_bfloat16* VHg = g_vx_h + (size_t)bh * SSEQ * 64;
    const __nv_bfloat16* VLg = g_vx_l + (size_t)bh * SSEQ * 64;

    auto prefetch = [&](int kt) {
        uint32_t d = sb0 + F_STG + (uint32_t)(kt & 1) * F_SSZ;
        const int s0 = kt * 64;
#pragma unroll
        for (int it = 0; it < 4; it++) {
            int idx = tid + it * 256;
            int r = idx >> 4, g = idx & 15;
            cpa16(d +        r * 272 + g * 16, KHg + (size_t)(s0 + r) * 128 + g * 8);
            cpa16(d + F_KL + r * 272 + g * 16, KLg + (size_t)(s0 + r) * 128 + g * 8);
        }
#pragma unroll
        for (int it = 0; it < 2; it++) {
            int idx = tid + it * 256;
            int r = idx >> 3, g = idx & 7;
            cpa16(d + F_VH + r * 144 + g * 16, VHg + (size_t)(s0 + r) * 64 + g * 8);
            cpa16(d + F_VL + r * 144 + g * 16, VLg + (size_t)(s0 + r) * 64 + g * 8);
        }
    };

    prefetch(0);
    CP_COMMIT();

    // ---- preload Q fragments (ql only for ks<4 — QJ-lo dropped) ----
    uint32_t qh[8][4], ql[4][4];
#pragma unroll
    for (int ks = 0; ks < 8; ks++) {
        uint32_t ad = sb0 + F_QH + (uint32_t)((w * 16 + (lane & 15)) * 272
                                              + (ks * 16 + (lane >> 4) * 8) * 2);
        ldsm4(qh[ks], ad);
        if (ks < 4) ldsm4(ql[ks], ad + F_QL);
    }

    float o[8][4];
#pragma unroll
    for (int i = 0; i < 8; i++)
#pragma unroll
        for (int t = 0; t < 4; t++) o[i][t] = 0.f;
    float mrow[2] = { -1e30f, -1e30f };
    float lsum[2] = { 0.f, 0.f };

    for (int kt = 0; kt < SSEQ / 64; kt++) {
        if (kt + 1 < SSEQ / 64) {
            prefetch(kt + 1);
            CP_COMMIT();
            CP_WAIT1();
        } else {
            CP_WAIT0();
        }
        __syncthreads();

        const uint32_t sb = sb0 + F_STG + (uint32_t)(kt & 1) * F_SSZ;

        // ---- S = Q' . K'^T — per ks: hoist K frags, then independent passes ----
        float s[8][4];
#pragma unroll
        for (int i = 0; i < 8; i++)
#pragma unroll
            for (int t = 0; t < 4; t++) s[i][t] = 0.f;
#pragma unroll
        for (int ks = 0; ks < 8; ks++) {
            uint32_t kh[4][4], kl[4][4];
#pragma unroll
            for (int u = 0; u < 4; u++) {
                uint32_t bd = sb + (uint32_t)((u * 16 + (lane & 7) + ((lane >> 4) & 1) * 8) * 272
                                              + (ks * 16 + ((lane >> 3) & 1) * 8) * 2);
                ldsm4(kh[u], bd);
                ldsm4(kl[u], bd + F_KL);
            }
            // pass 1: qh * kh (8 independent)
#pragma unroll
            for (int u = 0; u < 4; u++) {
                mma_bf16(s[2 * u],     qh[ks], kh[u][0], kh[u][1]);
                mma_bf16(s[2 * u + 1], qh[ks], kh[u][2], kh[u][3]);
            }
            // pass 2: qh * kl
#pragma unroll
            for (int u = 0; u < 4; u++) {
                mma_bf16(s[2 * u],     qh[ks], kl[u][0], kl[u][1]);
                mma_bf16(s[2 * u + 1], qh[ks], kl[u][2], kl[u][3]);
            }
            // pass 3: ql * kh (raw-Q half only)
            if (ks < 4) {
#pragma unroll
                for (int u = 0; u < 4; u++) {
                    mma_bf16(s[2 * u],     ql[ks], kh[u][0], kh[u][1]);
                    mma_bf16(s[2 * u + 1], ql[ks], kh[u][2], kh[u][3]);
                }
            }
        }

        // ---- online softmax ----
#pragma unroll
        for (int rr = 0; rr < 2; rr++) {
            float rm = -1e30f;
#pragma unroll
            for (int nt = 0; nt < 8; nt++) {
                rm = fmaxf(rm, s[nt][rr * 2 + 0]);
                rm = fmaxf(rm, s[nt][rr * 2 + 1]);
            }
            rm = fmaxf(rm, __shfl_xor_sync(0xffffffffu, rm, 1));
            rm = fmaxf(rm, __shfl_xor_sync(0xffffffffu, rm, 2));
            const float mnew = fmaxf(mrow[rr], rm);
            const float alpha = __expf(mrow[rr] - mnew);
            mrow[rr] = mnew;
            float rs = 0.f;
#pragma unroll
            for (int nt = 0; nt < 8; nt++) {
                float p0 = __expf(s[nt][rr * 2 + 0] - mnew);
                float p1 = __expf(s[nt][rr * 2 + 1] - mnew);
                s[nt][rr * 2 + 0] = p0;
                s[nt][rr * 2 + 1] = p1;
                rs += p0 + p1;
            }
            rs += __shfl_xor_sync(0xffffffffu, rs, 1);
            rs += __shfl_xor_sync(0xffffffffu, rs, 2);
            lsum[rr] = lsum[rr] * alpha + rs;
#pragma unroll
            for (int nt = 0; nt < 8; nt++) {
                o[nt][rr * 2 + 0] *= alpha;
                o[nt][rr * 2 + 1] *= alpha;
            }
        }

        // ---- O += P @ V — per t: hoist V frags, independent passes ----
#pragma unroll
        for (int t = 0; t < 4; t++) {
            uint32_t ph[4], pl[4];
            ph[0] = packbf(s[2 * t][0], s[2 * t][1]);
            pl[0] = packbf(s[2 * t][0] - bflo(ph[0]), s[2 * t][1] - bfhi(ph[0]));
            ph[1] = packbf(s[2 * t][2], s[2 * t][3]);
            pl[1] = packbf(s[2 * t][2] - bflo(ph[1]), s[2 * t][3] - bfhi(ph[1]));
            ph[2] = packbf(s[2 * t + 1][0], s[2 * t + 1][1]);
            pl[2] = packbf(s[2 * t + 1][0] - bflo(ph[2]), s[2 * t + 1][1] - bfhi(ph[2]));
            ph[3] = packbf(s[2 * t + 1][2], s[2 * t + 1][3]);
            pl[3] = packbf(s[2 * t + 1][2] - bflo(ph[3]), s[2 * t + 1][3] - bfhi(ph[3]));
            uint32_t vh[4][4], vl[4][4];
#pragma unroll
            for (int u = 0; u < 4; u++) {
                uint32_t vd = sb + F_VH
                    + (uint32_t)((t * 16 + (lane & 7) + ((lane >> 3) & 1) * 8) * 144
                                 + (u * 16 + ((lane >> 4) & 1) * 8) * 2);
                ldsm4t(vh[u], vd);
                ldsm4t(vl[u], vd + (F_VL - F_VH));
            }
            // pass 1: ph * vh
#pragma unroll
            for (int u = 0; u < 4; u++) {
                mma_bf16(o[2 * u],     ph, vh[u][0], vh[u][1]);
                mma_bf16(o[2 * u + 1], ph, vh[u][2], vh[u][3]);
            }
            // pass 2: ph * vl
#pragma unroll
            for (int u = 0; u < 4; u++) {
                mma_bf16(o[2 * u],     ph, vl[u][0], vl[u][1]);
                mma_bf16(o[2 * u + 1], ph, vl[u][2], vl[u][3]);
            }
            // pass 3: pl * vh
#pragma unroll
            for (int u = 0; u < 4; u++) {
                mma_bf16(o[2 * u],     pl, vh[u][0], vh[u][1]);
                mma_bf16(o[2 * u + 1], pl, vh[u][2], vh[u][3]);
            }
        }
        __syncthreads();
    }

    // ---- epilogue: ctx (bf16 hi/lo) = O / l ----
    const float inv0 = 1.f / lsum[0];
    const float inv1 = 1.f / lsum[1];
    const int r0 = qt * 128 + w * 16 + (lane >> 2);
#pragma unroll
    for (int nt = 0; nt < 8; nt++) {
        const int d = h * DH + nt * 8 + (lane & 3) * 2;
        {
            const size_t i0 = ((size_t)b * SSEQ + r0) * EMB + d;
            float v0 = o[nt][0] * inv0, v1 = o[nt][1] * inv0;
            uint32_t hh = packbf(v0, v1);
            uint32_t ll = packbf(v0 - bflo(hh), v1 - bfhi(hh));
            *(uint32_t*)&g_ctx_h[i0] = hh;
            *(uint32_t*)&g_ctx_l[i0] = ll;
        }
        {
            const size_t i1 = ((size_t)b * SSEQ + r0 + 8) * EMB + d;
            float v0 = o[nt][2] * inv1, v1 = o[nt][3] * inv1;
            uint32_t hh = packbf(v0, v1);
            uint32_t ll = packbf(v0 - bflo(hh), v1 - bfhi(hh));
            *(uint32_t*)&g_ctx_h[i1] = hh;
            *(uint32_t*)&g_ctx_l[i1] = ll;
        }
    }
}

// ============================================================================
extern "C" void kernel_launch(void* const* d_in, const int* in_sizes, int n_in,
                              void* d_out, int out_size)
{
    const float* x   = (const float*)d_in[0];
    const float* Wq  = (const float*)d_in[1];
    const float* bq  = (const float*)d_in[2];
    const float* Wk  = (const float*)d_in[3];
    const float* bk  = (const float*)d_in[4];
    const float* Wv  = (const float*)d_in[5];
    const float* bv  = (const float*)d_in[6];
    const float* Wo  = (const float*)d_in[7];
    const float* bo  = (const float*)d_in[8];
    const float* J   = (const float*)d_in[9];
    const float* lam = (const float*)d_in[10];
    float* out = (float*)d_out;
    (void)in_sizes; (void)n_in; (void)out_size;

    __nv_bfloat16 *xh, *xl, *wh, *wl, *ch, *cl;
    cudaGetSymbolAddress((void**)&xh, g_xh);
    cudaGetSymbolAddress((void**)&xl, g_xl);
    cudaGetSymbolAddress((void**)&wh, g_wh);
    cudaGetSymbolAddress((void**)&wl, g_wl);
    cudaGetSymbolAddress((void**)&ch, g_ctx_h);
    cudaGetSymbolAddress((void**)&cl, g_ctx_l);

    conv_split<<<(MTOT * EMB / 4) / 256, 256>>>(x, xh, xl, MTOT * EMB / 4);
    conv_split<<<(EMB * EMB / 4) / 256, 256>>>(Wq, wh + 0 * WSZ, wl + 0 * WSZ, EMB * EMB / 4);
    conv_split<<<(EMB * EMB / 4) / 256, 256>>>(Wk, wh + 1 * WSZ, wl + 1 * WSZ, EMB * EMB / 4);
    conv_split<<<(EMB * EMB / 4) / 256, 256>>>(Wv, wh + 2 * WSZ, wl + 2 * WSZ, EMB * EMB / 4);
    conv_split<<<(EMB * EMB / 4) / 256, 256>>>(Wo, wh + 3 * WSZ, wl + 3 * WSZ, EMB * EMB / 4);

    const int gsmem = 3 * 40960;   // 120KB
    cudaFuncSetAttribute(gemm_bf16<0>, cudaFuncAttributeMaxDynamicSharedMemorySize, gsmem);
    cudaFuncSetAttribute(gemm_bf16<1>, cudaFuncAttributeMaxDynamicSharedMemorySize, gsmem);
    cudaFuncSetAttribute(flash_mma, cudaFuncAttributeMaxDynamicSharedMemorySize, F_TOT);

    gemm_bf16<0><<<dim3(EMB / 128, MTOT / 128, 3), 256, gsmem>>>(
        xh, xl, bq, bk, bv, nullptr);

    flash_mma<<<dim3(SSEQ / 128, BB * HH), 256, F_TOT>>>(J, lam);

    gemm_bf16<1><<<dim3(EMB / 128, MTOT / 128, 1), 256, gsmem>>>(
        ch, cl, bo, nullptr, nullptr, out);
}

// round 17
// speedup vs baseline: 1.0396x; 1.0031x over previous
#include <cuda_runtime.h>
#include <cuda_bf16.h>
#include <cstdint>
#include <math.h>

#define BB   2
#define HH   16
#define SSEQ 2048
#define DH   64
#define EMB  1024
#define MTOT (BB * SSEQ)   // 4096
#define WSZ  ((size_t)EMB * EMB)

// ---- scratch (no allocation allowed) ----
__device__ float g_q[(size_t)BB * HH * SSEQ * DH];            // [B,H,S,D] fp32
__device__ __nv_bfloat16 g_xh[(size_t)MTOT * EMB];
__device__ __nv_bfloat16 g_xl[(size_t)MTOT * EMB];
__device__ __nv_bfloat16 g_wh[4 * WSZ];                        // Wq,Wk,Wv,Wo
__device__ __nv_bfloat16 g_wl[4 * WSZ];
__device__ __nv_bfloat16 g_ctx_h[(size_t)MTOT * EMB];          // attn output
__device__ __nv_bfloat16 g_ctx_l[(size_t)MTOT * EMB];
// K' = [K | tanh(K)] bf16 hi/lo split, [bh][s][128]
__device__ __nv_bfloat16 g_kx_h[(size_t)BB * HH * SSEQ * 128];
__device__ __nv_bfloat16 g_kx_l[(size_t)BB * HH * SSEQ * 128];
// V bf16 hi/lo split, [bh][s][64]
__device__ __nv_bfloat16 g_vx_h[(size_t)BB * HH * SSEQ * 64];
__device__ __nv_bfloat16 g_vx_l[(size_t)BB * HH * SSEQ * 64];

// ============================================================================
// helpers
// ============================================================================
__device__ __forceinline__ uint32_t smem_u32(const void* p) {
    uint32_t a;
    asm("{ .reg .u64 t; cvta.to.shared.u64 t, %1; cvt.u32.u64 %0, t; }" : "=r"(a) : "l"(p));
    return a;
}
__device__ __forceinline__ void ldsm4(uint32_t* r, uint32_t addr) {
    asm volatile("ldmatrix.sync.aligned.m8n8.x4.shared.b16 {%0,%1,%2,%3}, [%4];"
        : "=r"(r[0]), "=r"(r[1]), "=r"(r[2]), "=r"(r[3]) : "r"(addr));
}
__device__ __forceinline__ void ldsm4t(uint32_t* r, uint32_t addr) {
    asm volatile("ldmatrix.sync.aligned.m8n8.x4.trans.shared.b16 {%0,%1,%2,%3}, [%4];"
        : "=r"(r[0]), "=r"(r[1]), "=r"(r[2]), "=r"(r[3]) : "r"(addr));
}
// D += A(bf16 m16k16) * B(bf16 k16n8), fp32 accum
__device__ __forceinline__ void mma_bf16(float* d, const uint32_t* a, uint32_t b0, uint32_t b1) {
    asm volatile("mma.sync.aligned.m16n8k16.row.col.f32.bf16.bf16.f32 "
        "{%0,%1,%2,%3}, {%4,%5,%6,%7}, {%8,%9}, {%0,%1,%2,%3};"
        : "+f"(d[0]), "+f"(d[1]), "+f"(d[2]), "+f"(d[3])
        : "r"(a[0]), "r"(a[1]), "r"(a[2]), "r"(a[3]), "r"(b0), "r"(b1));
}
__device__ __forceinline__ uint32_t packbf(float lo, float hi) {
    uint32_t r;
    asm("cvt.rn.bf16x2.f32 %0, %1, %2;" : "=r"(r) : "f"(hi), "f"(lo));
    return r;
}
__device__ __forceinline__ float bflo(uint32_t u) { return __uint_as_float(u << 16); }
__device__ __forceinline__ float bfhi(uint32_t u) { return __uint_as_float(u & 0xffff0000u); }

__device__ __forceinline__ void split4(float4 v, uint32_t& h0, uint32_t& h1,
                                       uint32_t& l0, uint32_t& l1) {
    h0 = packbf(v.x, v.y);
    h1 = packbf(v.z, v.w);
    l0 = packbf(v.x - bflo(h0), v.y - bfhi(h0));
    l1 = packbf(v.z - bflo(h1), v.w - bfhi(h1));
}

__device__ __forceinline__ void cpa16(uint32_t dst, const void* src) {
    asm volatile("cp.async.cg.shared.global [%0], [%1], 16;" :: "r"(dst), "l"(src));
}
#define CP_COMMIT() asm volatile("cp.async.commit_group;" ::: "memory")
#define CP_WAIT1()  asm volatile("cp.async.wait_group 1;" ::: "memory")
#define CP_WAIT0()  asm volatile("cp.async.wait_group 0;" ::: "memory")

// ============================================================================
// pre-pass: fp32 -> bf16 hi/lo residual split
// ============================================================================
__global__ __launch_bounds__(256)
void conv_split(const float* __restrict__ src, __nv_bfloat16* __restrict__ dh,
                __nv_bfloat16* __restrict__ dl, int n4)
{
    int i = blockIdx.x * 256 + threadIdx.x;
    if (i < n4) {
        float4 v = ((const float4*)src)[i];
        uint32_t h0, h1, l0, l1;
        split4(v, h0, h1, l0, l1);
        ((uint2*)dh)[i] = make_uint2(h0, h1);
        ((uint2*)dl)[i] = make_uint2(l0, l1);
    }
}

// ============================================================================
// HMMA GEMM on pre-split bf16 operands: C = A @ W^T + bias.
// CTA tile 128x128, K-chunk 32, 3-stage cp.async pipeline, 8 warps (2Mx4N),
// warp tile 64x32. MMA stream reordered into 3 passes of 16 independent MMAs
// (accumulator reuse distance 16 — no RAW issue stalls).
// ============================================================================
template <int OPROJ>
__global__ __launch_bounds__(256, 1)
void gemm_bf16(const __nv_bfloat16* __restrict__ Ah,
               const __nv_bfloat16* __restrict__ Al,
               const float* __restrict__ b0p, const float* __restrict__ b1p,
               const float* __restrict__ b2p, float* __restrict__ Oout)
{
    extern __shared__ __align__(16) char dyn[];
    const int tid = threadIdx.x;
    const int lane = tid & 31;
    const int wid = tid >> 5;
    const int bm = blockIdx.y << 7;
    const int bn = blockIdx.x << 7;
    const int z = OPROJ ? 3 : (int)blockIdx.z;

    const float* bias = OPROJ ? b0p : (z == 0) ? b0p : (z == 1) ? b1p : b2p;

    const int wm = (wid >> 2) * 64;
    const int wn = (wid & 3) * 32;

    const __nv_bfloat16* srcs[4];
    srcs[0] = Ah + (size_t)bm * EMB;
    srcs[1] = Al + (size_t)bm * EMB;
    srcs[2] = g_wh + (size_t)z * WSZ + (size_t)bn * EMB;
    srcs[3] = g_wl + (size_t)z * WSZ + (size_t)bn * EMB;
    const uint32_t sbase = smem_u32(dyn);

    auto prefetch = [&](int c) {
        const uint32_t st = sbase + (uint32_t)(c % 3) * 40960u;
        const int kc = c * 32;
#pragma unroll
        for (int t = 0; t < 4; t++) {
#pragma unroll
            for (int j = 0; j < 2; j++) {
                int idx = tid + j * 256;
                int r = idx >> 2, g = idx & 3;
                cpa16(st + (uint32_t)(t * 10240 + r * 80 + g * 16),
                      srcs[t] + (size_t)r * EMB + kc + g * 8);
            }
        }
    };

    float acc[4][4][4];
#pragma unroll
    for (int i = 0; i < 4; i++)
#pragma unroll
        for (int j = 0; j < 4; j++)
#pragma unroll
            for (int t = 0; t < 4; t++) acc[i][j][t] = 0.f;

    prefetch(0); CP_COMMIT();
    prefetch(1); CP_COMMIT();

    for (int c = 0; c < 32; c++) {
        if (c + 2 < 32) CP_WAIT1(); else CP_WAIT0();
        __syncthreads();
        if (c + 2 < 32) { prefetch(c + 2); CP_COMMIT(); }

        const uint32_t sb = sbase + (uint32_t)(c % 3) * 40960u;
#pragma unroll
        for (int ks = 0; ks < 2; ks++) {
            uint32_t ah[4][4], al[4][4];
#pragma unroll
            for (int mt = 0; mt < 4; mt++) {
                uint32_t ad = sb + (uint32_t)((wm + mt * 16 + (lane & 15)) * 80
                                              + (ks * 16 + (lane >> 4) * 8) * 2);
                ldsm4(ah[mt], ad);
                ldsm4(al[mt], ad + 10240);
            }
            uint32_t bh[4][2], bl[4][2];
#pragma unroll
            for (int u = 0; u < 2; u++) {
                uint32_t bd = sb + 20480u
                    + (uint32_t)((wn + u * 16 + (lane & 7) + ((lane >> 4) & 1) * 8) * 80
                                 + (ks * 16 + ((lane >> 3) & 1) * 8) * 2);
                uint32_t r4[4];
                ldsm4(r4, bd);
                bh[2 * u][0] = r4[0]; bh[2 * u][1] = r4[1];
                bh[2 * u + 1][0] = r4[2]; bh[2 * u + 1][1] = r4[3];
                ldsm4(r4, bd + 10240);
                bl[2 * u][0] = r4[0]; bl[2 * u][1] = r4[1];
                bl[2 * u + 1][0] = r4[2]; bl[2 * u + 1][1] = r4[3];
            }
            // pass 1: Ah*Bh (16 independent MMAs)
#pragma unroll
            for (int mt = 0; mt < 4; mt++)
#pragma unroll
                for (int nt = 0; nt < 4; nt++)
                    mma_bf16(acc[mt][nt], ah[mt], bh[nt][0], bh[nt][1]);
            // pass 2: Ah*Bl
#pragma unroll
            for (int mt = 0; mt < 4; mt++)
#pragma unroll
                for (int nt = 0; nt < 4; nt++)
                    mma_bf16(acc[mt][nt], ah[mt], bl[nt][0], bl[nt][1]);
            // pass 3: Al*Bh
#pragma unroll
            for (int mt = 0; mt < 4; mt++)
#pragma unroll
                for (int nt = 0; nt < 4; nt++)
                    mma_bf16(acc[mt][nt], al[mt], bh[nt][0], bh[nt][1]);
        }
        __syncthreads();
    }

    // ---- epilogue ----
#pragma unroll
    for (int mt = 0; mt < 4; mt++)
#pragma unroll
        for (int nt = 0; nt < 4; nt++)
#pragma unroll
            for (int half = 0; half < 2; half++) {
                const int m = bm + wm + mt * 16 + (lane >> 2) + half * 8;
                const int n = bn + wn + nt * 8 + (lane & 3) * 2;
                float v0 = acc[mt][nt][half * 2 + 0] + bias[n];
                float v1 = acc[mt][nt][half * 2 + 1] + bias[n + 1];
                if (OPROJ) {
                    *(float2*)(Oout + (size_t)m * EMB + n) = make_float2(v0, v1);
                } else if (z == 0) {
                    const int hh = n >> 6, d = n & 63;
                    const int bq = m >> 11, s = m & 2047;
                    *(float2*)(&g_q[(((size_t)bq * HH + hh) * SSEQ + s) * DH + d]) =
                        make_float2(v0, v1);
                } else {
                    const int bhd = (m >> 11) * HH + (n >> 6);
                    const int d = n & 63, s = m & 2047;
                    uint32_t h0 = packbf(v0, v1);
                    uint32_t l0 = packbf(v0 - bflo(h0), v1 - bfhi(h0));
                    if (z == 1) {
                        const size_t base = ((size_t)bhd * SSEQ + s) * 128 + d;
                        *(uint32_t*)&g_kx_h[base] = h0;
                        *(uint32_t*)&g_kx_l[base] = l0;
                        float t0 = tanhf(v0), t1 = tanhf(v1);
                        uint32_t th = packbf(t0, t1);
                        uint32_t tl = packbf(t0 - bflo(th), t1 - bfhi(th));
                        *(uint32_t*)&g_kx_h[base + 64] = th;
                        *(uint32_t*)&g_kx_l[base + 64] = tl;
                    } else {
                        const size_t base = ((size_t)bhd * SSEQ + s) * 64 + d;
                        *(uint32_t*)&g_vx_h[base] = h0;
                        *(uint32_t*)&g_vx_l[base] = l0;
                    }
                }
            }
}

// ============================================================================
// Flash attention (HMMA), MMA streams reordered into independent passes.
// Score ks 0..3 (raw-Q half): 3 products; ks 4..7 (lam*QJ half): 2 products
// (QJ-lo cross dropped; |err| ~ 3e-4 absolute on scores, within 1e-3 gate).
// ============================================================================
#define F_QH   0
#define F_QL   34816
#define F_STG  69632
#define F_SSZ  53248
#define F_KL   17408
#define F_VH   34816
#define F_VL   44032
#define F_TOT  176128

__global__ __launch_bounds__(256, 1)
void flash_mma(const float* __restrict__ Jg, const float* __restrict__ lam_ptr)
{
    extern __shared__ __align__(16) char dyn[];
    const int tid = threadIdx.x;
    const int lane = tid & 31;
    const int w = tid >> 5;
    const int qt = blockIdx.x;
    const int bh = blockIdx.y;
    const int h = bh & (HH - 1);
    const int b = bh >> 4;
    const float lam = *lam_ptr;
    const uint32_t sb0 = smem_u32(dyn);

    float* QS = (float*)(dyn + F_STG);   // 128 x 132 fp32
    float* TQ = (float*)(dyn);           // 128 x 68  fp32
    float* JS = (float*)(dyn + 34816);   // 64 x 68   fp32

    // ---- prologue: Q raw + tanh(Q), J ----
    const float* Qb = g_q + ((size_t)bh * SSEQ + (size_t)qt * 128) * DH;
#pragma unroll
    for (int it = 0; it < 8; it++) {
        int idx = tid + it * 256;
        int r = idx >> 4, c = (idx & 15) << 2;
        float4 v = *(const float4*)(Qb + r * DH + c);
        QS[r * 132 + c + 0] = v.x; QS[r * 132 + c + 1] = v.y;
        QS[r * 132 + c + 2] = v.z; QS[r * 132 + c + 3] = v.w;
        TQ[r * 68 + c + 0] = tanhf(v.x); TQ[r * 68 + c + 1] = tanhf(v.y);
        TQ[r * 68 + c + 2] = tanhf(v.z); TQ[r * 68 + c + 3] = tanhf(v.w);
    }
    const float* Jb = Jg + (size_t)h * DH * DH;
#pragma unroll
    for (int it = 0; it < 4; it++) {
        int idx = tid + it * 256;
        int r = idx >> 4, c = (idx & 15) << 2;
        float4 v = *(const float4*)(Jb + r * DH + c);
        JS[r * 68 + c + 0] = v.x; JS[r * 68 + c + 1] = v.y;
        JS[r * 68 + c + 2] = v.z; JS[r * 68 + c + 3] = v.w;
    }
    __syncthreads();

    // ---- QJ = tanh(Q) @ J ----
    {
        const int tx = tid & 7, ty = tid >> 3;
        float a2[4][8];
#pragma unroll
        for (int i = 0; i < 4; i++)
#pragma unroll
            for (int j = 0; j < 8; j++) a2[i][j] = 0.f;
#pragma unroll 4
        for (int d0 = 0; d0 < 64; d0 += 4) {
            float a[4][4];
#pragma unroll
            for (int i = 0; i < 4; i++) {
                float4 t = *(const float4*)&TQ[(ty * 4 + i) * 68 + d0];
                a[i][0] = t.x; a[i][1] = t.y; a[i][2] = t.z; a[i][3] = t.w;
            }
#pragma unroll
            for (int dd = 0; dd < 4; dd++) {
                float bb[8];
#pragma unroll
                for (int j = 0; j < 8; j++) bb[j] = JS[(d0 + dd) * 68 + tx + j * 8];
#pragma unroll
                for (int i = 0; i < 4; i++)
#pragma unroll
                    for (int j = 0; j < 8; j++) a2[i][j] += a[i][dd] * bb[j];
            }
        }
#pragma unroll
        for (int i = 0; i < 4; i++) {
            int r = ty * 4 + i;
#pragma unroll
            for (int j = 0; j < 8; j++) {
                int c = tx + j * 8;
                QS[r * 132 + 64 + c] = lam * a2[i][j];
                QS[r * 132 + c] *= 0.125f;
            }
        }
    }
    __syncthreads();

    // ---- convert QS fp32 -> Qh/Ql bf16 tiles ----
#pragma unroll
    for (int it = 0; it < 16; it++) {
        int idx = tid + it * 256;
        int r = idx >> 5, g = idx & 31;
        float4 v = *(const float4*)&QS[r * 132 + g * 4];
        uint32_t h0, h1, l0, l1;
        split4(v, h0, h1, l0, l1);
        *(uint2*)(dyn + F_QH + r * 272 + g * 8) = make_uint2(h0, h1);
        *(uint2*)(dyn + F_QL + r * 272 + g * 8) = make_uint2(l0, l1);
    }
    __syncthreads();

    const __nv_bfloat16* KHg = g_kx_h + (size_t)bh * SSEQ * 128;
    const __nv_bfloat16* KLg = g_kx_l + (size_t)bh * SSEQ * 128;
    const __nv_bfloat16* VHg = g_vx_h + (size_t)bh * SSEQ * 64;
    const __nv_bfloat16* VLg = g_vx_l + (size_t)bh * SSEQ * 64;

    auto prefetch = [&](int kt) {
        uint32_t d = sb0 + F_STG + (uint32_t)(kt & 1) * F_SSZ;
        const int s0 = kt * 64;
#pragma unroll
        for (int it = 0; it < 4; it++) {
            int idx = tid + it * 256;
            int r = idx >> 4, g = idx & 15;
            cpa16(d +        r * 272 + g * 16, KHg + (size_t)(s0 + r) * 128 + g * 8);
            cpa16(d + F_KL + r * 272 + g * 16, KLg + (size_t)(s0 + r) * 128 + g * 8);
        }
#pragma unroll
        for (int it = 0; it < 2; it++) {
            int idx = tid + it * 256;
            int r = idx >> 3, g = idx & 7;
            cpa16(d + F_VH + r * 144 + g * 16, VHg + (size_t)(s0 + r) * 64 + g * 8);
            cpa16(d + F_VL + r * 144 + g * 16, VLg + (size_t)(s0 + r) * 64 + g * 8);
        }
    };

    prefetch(0);
    CP_COMMIT();

    // ---- preload Q fragments (ql only for ks<4 — QJ-lo dropped) ----
    uint32_t qh[8][4], ql[4][4];
#pragma unroll
    for (int ks = 0; ks < 8; ks++) {
        uint32_t ad = sb0 + F_QH + (uint32_t)((w * 16 + (lane & 15)) * 272
                                              + (ks * 16 + (lane >> 4) * 8) * 2);
        ldsm4(qh[ks], ad);
        if (ks < 4) ldsm4(ql[ks], ad + F_QL);
    }

    float o[8][4];
#pragma unroll
    for (int i = 0; i < 8; i++)
#pragma unroll
        for (int t = 0; t < 4; t++) o[i][t] = 0.f;
    float mrow[2] = { -1e30f, -1e30f };
    float lsum[2] = { 0.f, 0.f };

    for (int kt = 0; kt < SSEQ / 64; kt++) {
        if (kt + 1 < SSEQ / 64) {
            prefetch(kt + 1);
            CP_COMMIT();
            CP_WAIT1();
        } else {
            CP_WAIT0();
        }
        __syncthreads();

        const uint32_t sb = sb0 + F_STG + (uint32_t)(kt & 1) * F_SSZ;

        // ---- S = Q' . K'^T — per ks: hoist K frags, then independent passes ----
        float s[8][4];
#pragma unroll
        for (int i = 0; i < 8; i++)
#pragma unroll
            for (int t = 0; t < 4; t++) s[i][t] = 0.f;
#pragma unroll
        for (int ks = 0; ks < 8; ks++) {
            uint32_t kh[4][4], kl[4][4];
#pragma unroll
            for (int u = 0; u < 4; u++) {
                uint32_t bd = sb + (uint32_t)((u * 16 + (lane & 7) + ((lane >> 4) & 1) * 8) * 272
                                              + (ks * 16 + ((lane >> 3) & 1) * 8) * 2);
                ldsm4(kh[u], bd);
                ldsm4(kl[u], bd + F_KL);
            }
            // pass 1: qh * kh (8 independent)
#pragma unroll
            for (int u = 0; u < 4; u++) {
                mma_bf16(s[2 * u],     qh[ks], kh[u][0], kh[u][1]);
                mma_bf16(s[2 * u + 1], qh[ks], kh[u][2], kh[u][3]);
            }
            // pass 2: qh * kl
#pragma unroll
            for (int u = 0; u < 4; u++) {
                mma_bf16(s[2 * u],     qh[ks], kl[u][0], kl[u][1]);
                mma_bf16(s[2 * u + 1], qh[ks], kl[u][2], kl[u][3]);
            }
            // pass 3: ql * kh (raw-Q half only)
            if (ks < 4) {
#pragma unroll
                for (int u = 0; u < 4; u++) {
                    mma_bf16(s[2 * u],     ql[ks], kh[u][0], kh[u][1]);
                    mma_bf16(s[2 * u + 1], ql[ks], kh[u][2], kh[u][3]);
                }
            }
        }

        // ---- online softmax ----
#pragma unroll
        for (int rr = 0; rr < 2; rr++) {
            float rm = -1e30f;
#pragma unroll
            for (int nt = 0; nt < 8; nt++) {
                rm = fmaxf(rm, s[nt][rr * 2 + 0]);
                rm = fmaxf(rm, s[nt][rr * 2 + 1]);
            }
            rm = fmaxf(rm, __shfl_xor_sync(0xffffffffu, rm, 1));
            rm = fmaxf(rm, __shfl_xor_sync(0xffffffffu, rm, 2));
            const float mnew = fmaxf(mrow[rr], rm);
            const float alpha = __expf(mrow[rr] - mnew);
            mrow[rr] = mnew;
            float rs = 0.f;
#pragma unroll
            for (int nt = 0; nt < 8; nt++) {
                float p0 = __expf(s[nt][rr * 2 + 0] - mnew);
                float p1 = __expf(s[nt][rr * 2 + 1] - mnew);
                s[nt][rr * 2 + 0] = p0;
                s[nt][rr * 2 + 1] = p1;
                rs += p0 + p1;
            }
            rs += __shfl_xor_sync(0xffffffffu, rs, 1);
            rs += __shfl_xor_sync(0xffffffffu, rs, 2);
            lsum[rr] = lsum[rr] * alpha + rs;
#pragma unroll
            for (int nt = 0; nt < 8; nt++) {
                o[nt][rr * 2 + 0] *= alpha;
                o[nt][rr * 2 + 1] *= alpha;
            }
        }

        // ---- O += P @ V — per t: hoist V frags, independent passes ----
#pragma unroll
        for (int t = 0; t < 4; t++) {
            uint32_t ph[4], pl[4];
            ph[0] = packbf(s[2 * t][0], s[2 * t][1]);
            pl[0] = packbf(s[2 * t][0] - bflo(ph[0]), s[2 * t][1] - bfhi(ph[0]));
            ph[1] = packbf(s[2 * t][2], s[2 * t][3]);
            pl[1] = packbf(s[2 * t][2] - bflo(ph[1]), s[2 * t][3] - bfhi(ph[1]));
            ph[2] = packbf(s[2 * t + 1][0], s[2 * t + 1][1]);
            pl[2] = packbf(s[2 * t + 1][0] - bflo(ph[2]), s[2 * t + 1][1] - bfhi(ph[2]));
            ph[3] = packbf(s[2 * t + 1][2], s[2 * t + 1][3]);
            pl[3] = packbf(s[2 * t + 1][2] - bflo(ph[3]), s[2 * t + 1][3] - bfhi(ph[3]));
            uint32_t vh[4][4], vl[4][4];
#pragma unroll
            for (int u = 0; u < 4; u++) {
                uint32_t vd = sb + F_VH
                    + (uint32_t)((t * 16 + (lane & 7) + ((lane >> 3) & 1) * 8) * 144
                                 + (u * 16 + ((lane >> 4) & 1) * 8) * 2);
                ldsm4t(vh[u], vd);
                ldsm4t(vl[u], vd + (F_VL - F_VH));
            }
            // pass 1: ph * vh
#pragma unroll
            for (int u = 0; u < 4; u++) {
                mma_bf16(o[2 * u],     ph, vh[u][0], vh[u][1]);
                mma_bf16(o[2 * u + 1], ph, vh[u][2], vh[u][3]);
            }
            // pass 2: ph * vl
#pragma unroll
            for (int u = 0; u < 4; u++) {
                mma_bf16(o[2 * u],     ph, vl[u][0], vl[u][1]);
                mma_bf16(o[2 * u + 1], ph, vl[u][2], vl[u][3]);
            }
            // pass 3: pl * vh
#pragma unroll
            for (int u = 0; u < 4; u++) {
                mma_bf16(o[2 * u],     pl, vh[u][0], vh[u][1]);
                mma_bf16(o[2 * u + 1], pl, vh[u][2], vh[u][3]);
            }
        }
        __syncthreads();
    }

    // ---- epilogue: ctx (bf16 hi/lo) = O / l ----
    const float inv0 = 1.f / lsum[0];
    const float inv1 = 1.f / lsum[1];
    const int r0 = qt * 128 + w * 16 + (lane >> 2);
#pragma unroll
    for (int nt = 0; nt < 8; nt++) {
        const int d = h * DH + nt * 8 + (lane & 3) * 2;
        {
            const size_t i0 = ((size_t)b * SSEQ + r0) * EMB + d;
            float v0 = o[nt][0] * inv0, v1 = o[nt][1] * inv0;
            uint32_t hh = packbf(v0, v1);
            uint32_t ll = packbf(v0 - bflo(hh), v1 - bfhi(hh));
            *(uint32_t*)&g_ctx_h[i0] = hh;
            *(uint32_t*)&g_ctx_l[i0] = ll;
        }
        {
            const size_t i1 = ((size_t)b * SSEQ + r0 + 8) * EMB + d;
            float v0 = o[nt][2] * inv1, v1 = o[nt][3] * inv1;
            uint32_t hh = packbf(v0, v1);
            uint32_t ll = packbf(v0 - bflo(hh), v1 - bfhi(hh));
            *(uint32_t*)&g_ctx_h[i1] = hh;
            *(uint32_t*)&g_ctx_l[i1] = ll;
        }
    }
}

// ============================================================================
extern "C" void kernel_launch(void* const* d_in, const int* in_sizes, int n_in,
                              void* d_out, int out_size)
{
    const float* x   = (const float*)d_in[0];
    const float* Wq  = (const float*)d_in[1];
    const float* bq  = (const float*)d_in[2];
    const float* Wk  = (const float*)d_in[3];
    const float* bk  = (const float*)d_in[4];
    const float* Wv  = (const float*)d_in[5];
    const float* bv  = (const float*)d_in[6];
    const float* Wo  = (const float*)d_in[7];
    const float* bo  = (const float*)d_in[8];
    const float* J   = (const float*)d_in[9];
    const float* lam = (const float*)d_in[10];
    float* out = (float*)d_out;
    (void)in_sizes; (void)n_in; (void)out_size;

    __nv_bfloat16 *xh, *xl, *wh, *wl, *ch, *cl;
    cudaGetSymbolAddress((void**)&xh, g_xh);
    cudaGetSymbolAddress((void**)&xl, g_xl);
    cudaGetSymbolAddress((void**)&wh, g_wh);
    cudaGetSymbolAddress((void**)&wl, g_wl);
    cudaGetSymbolAddress((void**)&ch, g_ctx_h);
    cudaGetSymbolAddress((void**)&cl, g_ctx_l);

    conv_split<<<(MTOT * EMB / 4) / 256, 256>>>(x, xh, xl, MTOT * EMB / 4);
    conv_split<<<(EMB * EMB / 4) / 256, 256>>>(Wq, wh + 0 * WSZ, wl + 0 * WSZ, EMB * EMB / 4);
    conv_split<<<(EMB * EMB / 4) / 256, 256>>>(Wk, wh + 1 * WSZ, wl + 1 * WSZ, EMB * EMB / 4);
    conv_split<<<(EMB * EMB / 4) / 256, 256>>>(Wv, wh + 2 * WSZ, wl + 2 * WSZ, EMB * EMB / 4);
    conv_split<<<(EMB * EMB / 4) / 256, 256>>>(Wo, wh + 3 * WSZ, wl + 3 * WSZ, EMB * EMB / 4);

    const int gsmem = 3 * 40960;   // 120KB
    cudaFuncSetAttribute(gemm_bf16<0>, cudaFuncAttributeMaxDynamicSharedMemorySize, gsmem);
    cudaFuncSetAttribute(gemm_bf16<1>, cudaFuncAttributeMaxDynamicSharedMemorySize, gsmem);
    cudaFuncSetAttribute(flash_mma, cudaFuncAttributeMaxDynamicSharedMemorySize, F_TOT);

    gemm_bf16<0><<<dim3(EMB / 128, MTOT / 128, 3), 256, gsmem>>>(
        xh, xl, bq, bk, bv, nullptr);

    flash_mma<<<dim3(SSEQ / 128, BB * HH), 256, F_TOT>>>(J, lam);

    gemm_bf16<1><<<dim3(EMB / 128, MTOT / 128, 1), 256, gsmem>>>(
        ch, cl, bo, nullptr, nullptr, out);
}